// round 14
// baseline (speedup 1.0000x reference)
#include <cuda_runtime.h>
#include <cuda.h>
#include <cuda_fp16.h>
#include <cstdint>

#define Bb   256
#define Nn   128
#define Dd   2048
#define DH   128
#define Mtot (Bb*Nn)   // 32768

// W in MMA-fragment block layout: block(kb,nb) = 8n x 16k fp16, 256 B;
// lane l owns uint2{b0,b1} at [(kb*16+nb)*32 + l]. kb=k/16 (128), nb=n/8 (16).
__device__ __align__(256) uint2 g_wb[(size_t)128 * 16 * 32];   // 512 KB

// ===================== PTX helpers =====================
__device__ __forceinline__ uint32_t smem_u32(const void* p) {
    uint32_t a;
    asm("{ .reg .u64 t; cvta.to.shared.u64 t, %1; cvt.u32.u64 %0, t; }" : "=r"(a) : "l"(p));
    return a;
}
__device__ __forceinline__ void mbar_init(uint32_t m, uint32_t cnt) {
    asm volatile("mbarrier.init.shared.b64 [%0], %1;" :: "r"(m), "r"(cnt) : "memory");
}
__device__ __forceinline__ void mbar_expect_tx(uint32_t m, uint32_t bytes) {
    asm volatile("mbarrier.arrive.expect_tx.shared.b64 _, [%0], %1;" :: "r"(m), "r"(bytes) : "memory");
}
__device__ __forceinline__ void mbar_wait(uint32_t m, uint32_t ph) {
    asm volatile(
        "{\n\t.reg .pred P;\n"
        "W%=:\n\t"
        "mbarrier.try_wait.parity.acquire.cta.shared::cta.b64 P, [%0], %1, 0x989680;\n\t"
        "@P bra D%=;\n\t"
        "bra W%=;\n"
        "D%=:\n\t}"
        :: "r"(m), "r"(ph) : "memory");
}
__device__ __forceinline__ void tma2d(uint32_t dst, const CUtensorMap* map, int x, int y, uint32_t mbar) {
    asm volatile(
        "cp.async.bulk.tensor.2d.shared::cta.global.tile.mbarrier::complete_tx::bytes "
        "[%0], [%1, {%2, %3}], [%4];"
        :: "r"(dst), "l"(map), "r"(x), "r"(y), "r"(mbar) : "memory");
}
__device__ __forceinline__ void mma16816(float* d, const uint32_t* a, uint32_t b0, uint32_t b1) {
    asm volatile(
        "mma.sync.aligned.m16n8k16.row.col.f32.f16.f16.f32 "
        "{%0,%1,%2,%3}, {%4,%5,%6,%7}, {%8,%9}, {%0,%1,%2,%3};"
        : "+f"(d[0]), "+f"(d[1]), "+f"(d[2]), "+f"(d[3])
        : "r"(a[0]), "r"(a[1]), "r"(a[2]), "r"(a[3]), "r"(b0), "r"(b1));
}
__device__ __forceinline__ float lrelu(float s) { return s > 0.f ? s : 0.2f * s; }
__device__ __forceinline__ uint32_t packh2(float2 v) {
    __half2 h = __float22half2_rn(v);
    return *reinterpret_cast<uint32_t*>(&h);
}
// SW128 swizzle (matches CU_TENSOR_MAP_SWIZZLE_128B): XOR 16B-chunk bits[6:4] with row bits[9:7]
#define SW(x) ((x) ^ ((((uint32_t)(x)) >> 3) & 0x70u))

// ===================== config =====================
#define KC        32
#define NTILE     (Dd / KC)               // 64
#define STAGES    4
#define FPA_STAGE (128 * KC * 4)          // 16384 B fp32 A tile (swizzled rows of 128 B)
#define OFF_FPA   1024
#define SMEMSZ    (OFF_FPA + STAGES * FPA_STAGE)   // 66560 -> 2 CTAs/SM

__global__ void __launch_bounds__(256, 2)
fused_gat(const float* __restrict__ Wbv, const float* __restrict__ bbv,
          const float* __restrict__ Wcv, const float* __restrict__ bcv,
          const float* __restrict__ bias, float* __restrict__ out,
          const __grid_constant__ CUtensorMap mapA)
{
    extern __shared__ char smem[];
    const uint32_t sb = smem_u32(smem);
    const int tid = threadIdx.x;
    const int lane = tid & 31, w = tid >> 5;
    const int g = lane >> 2, tig = lane & 3;
    const int wm = w & 3;        // m-block (32 rows)
    const int wn = w >> 2;       // n-block (64 cols)

    if (tid == 0) {
        #pragma unroll
        for (int s = 0; s < STAGES; s++) mbar_init(sb + 8 * s, 1);
    }
    __syncthreads();
    if (tid == 0) {
        #pragma unroll
        for (int s = 0; s < STAGES; s++) {
            mbar_expect_tx(sb + 8 * s, FPA_STAGE);
            tma2d(sb + OFF_FPA + s * FPA_STAGE, &mapA, s * KC, blockIdx.x * 128, sb + 8 * s);
        }
    }

    float acc[2][8][4];
    #pragma unroll
    for (int mt = 0; mt < 2; mt++)
        #pragma unroll
        for (int nt = 0; nt < 8; nt++)
            #pragma unroll
            for (int q = 0; q < 4; q++) acc[mt][nt][q] = 0.f;

    // per-warp B base
    const uint2* wbase = g_wb + (size_t)(wn * 8) * 32 + lane;
    // A frag base offsets within a stage (two rows per mt: r and r+8)
    const uint32_t arow0 = (uint32_t)(wm * 32 + g) * 128 + (uint32_t)tig * 8;

    #pragma unroll 1
    for (int t = 0; t < NTILE; t++) {
        // refill: stage (t-1)&3 was fully consumed by end of iter t-1 -> load tile t+3
        if (tid == 0 && t >= 1 && t + 3 < NTILE) {
            const int rs = (t + 3) & 3;
            mbar_expect_tx(sb + 8 * rs, FPA_STAGE);
            tma2d(sb + OFF_FPA + rs * FPA_STAGE, &mapA,
                  (t + 3) * KC, blockIdx.x * 128, sb + 8 * rs);
        }

        // B frags for tile t (issue early; latency hidden under wait + A loads)
        uint2 bblk[2][8];
        #pragma unroll
        for (int s = 0; s < 2; s++)
            #pragma unroll
            for (int nt = 0; nt < 8; nt++)
                bblk[s][nt] = __ldg(wbase + (size_t)((t * 2 + s) * 16 + nt) * 32);

        const int st = t & 3;
        mbar_wait(sb + 8 * st, (t >> 2) & 1);

        // A frags straight from swizzled fp32 tile: LDS.64 + cvt (conflict-free)
        const char* abase = smem + OFF_FPA + st * FPA_STAGE;
        uint32_t ah[2][2][4];   // [s][mt][r]
        #pragma unroll
        for (int s = 0; s < 2; s++) {
            #pragma unroll
            for (int mt = 0; mt < 2; mt++) {
                uint32_t o = arow0 + (uint32_t)(mt * 16) * 128 + (uint32_t)s * 64;
                float2 v0 = *reinterpret_cast<const float2*>(abase + SW(o));
                float2 v1 = *reinterpret_cast<const float2*>(abase + SW(o + 8 * 128));
                float2 v2 = *reinterpret_cast<const float2*>(abase + SW(o + 32));
                float2 v3 = *reinterpret_cast<const float2*>(abase + SW(o + 8 * 128 + 32));
                ah[s][mt][0] = packh2(v0);
                ah[s][mt][1] = packh2(v1);
                ah[s][mt][2] = packh2(v2);
                ah[s][mt][3] = packh2(v3);
            }
        }

        // MMA(t)
        #pragma unroll
        for (int s = 0; s < 2; s++)
            #pragma unroll
            for (int nt = 0; nt < 8; nt++)
                #pragma unroll
                for (int mt = 0; mt < 2; mt++)
                    mma16816(acc[mt][nt], ah[s][mt], bblk[s][nt].x, bblk[s][nt].y);

        __syncthreads();   // stage st fully consumed by all warps
    }

    // =============== fused epilogue: t1/t2, softmax(axis=i), output ===============
    float* eS1P = reinterpret_cast<float*>(smem);            // [128][2]
    float* eS2P = reinterpret_cast<float*>(smem + 1024);     // [128][2]
    float* eS1F = reinterpret_cast<float*>(smem + 2048);     // [128]
    float* eS2F = reinterpret_cast<float*>(smem + 2560);     // [128]
    float* eMX2 = reinterpret_cast<float*>(smem + 3072);     // [128][2]
    float* eZ2  = reinterpret_cast<float*>(smem + 4096);     // [128][2]
    float* eMX  = reinterpret_cast<float*>(smem + 5120);     // [128]
    float* eRZ  = reinterpret_cast<float*>(smem + 5632);     // [128]

    // (a) per-thread fragment dots with Wb/Wc
    float s1p[4] = {0.f, 0.f, 0.f, 0.f}, s2p[4] = {0.f, 0.f, 0.f, 0.f};
    #pragma unroll
    for (int nt = 0; nt < 8; nt++) {
        int c = wn * 64 + nt * 8 + 2 * tig;
        float wb0 = __ldg(Wbv + c), wb1 = __ldg(Wbv + c + 1);
        float wc0 = __ldg(Wcv + c), wc1 = __ldg(Wcv + c + 1);
        #pragma unroll
        for (int mt = 0; mt < 2; mt++) {
            s1p[mt * 2 + 0] += acc[mt][nt][0] * wb0 + acc[mt][nt][1] * wb1;
            s1p[mt * 2 + 1] += acc[mt][nt][2] * wb0 + acc[mt][nt][3] * wb1;
            s2p[mt * 2 + 0] += acc[mt][nt][0] * wc0 + acc[mt][nt][1] * wc1;
            s2p[mt * 2 + 1] += acc[mt][nt][2] * wc0 + acc[mt][nt][3] * wc1;
        }
    }
    // (b) reduce over tig
    #pragma unroll
    for (int off = 1; off <= 2; off <<= 1) {
        #pragma unroll
        for (int q = 0; q < 4; q++) {
            s1p[q] += __shfl_xor_sync(0xffffffffu, s1p[q], off);
            s2p[q] += __shfl_xor_sync(0xffffffffu, s2p[q], off);
        }
    }
    // (c) publish per-row partials per wn
    if (tig == 0) {
        #pragma unroll
        for (int q = 0; q < 4; q++) {
            int r = wm * 32 + (q >> 1) * 16 + (q & 1) * 8 + g;
            eS1P[r * 2 + wn] = s1p[q];
            eS2P[r * 2 + wn] = s2p[q];
        }
    }
    __syncthreads();
    // (d) finalize t1/t2
    if (tid < 128) {
        eS1F[tid] = eS1P[tid * 2] + eS1P[tid * 2 + 1] + bbv[0];
        eS2F[tid] = eS2P[tid * 2] + eS2P[tid * 2 + 1] + bcv[0];
    }
    __syncthreads();
    // (e) column softmax stats: 2 threads per column j
    {
        const int j = tid & 127, half = tid >> 7;
        const float s2j = eS2F[j];
        float m = -1e30f;
        #pragma unroll 4
        for (int i = half * 64; i < half * 64 + 64; i++)
            m = fmaxf(m, lrelu(eS1F[i] + s2j));
        eMX2[j * 2 + half] = m;
        __syncthreads();
        const float mj = fmaxf(eMX2[j * 2], eMX2[j * 2 + 1]);
        float z = 0.f;
        #pragma unroll 4
        for (int i = half * 64; i < half * 64 + 64; i++)
            z += __expf(lrelu(eS1F[i] + s2j) - mj);
        eZ2[j * 2 + half] = z;
        if (half == 0) eMX[j] = mj;
        __syncthreads();
        if (tid < 128) eRZ[tid] = 1.f / (eZ2[tid * 2] + eZ2[tid * 2 + 1]);
        __syncthreads();
    }
    // (f) output
    const size_t ob = (size_t)blockIdx.x * Nn * DH;
    float s1r[4];
    #pragma unroll
    for (int q = 0; q < 4; q++)
        s1r[q] = eS1F[wm * 32 + (q >> 1) * 16 + (q & 1) * 8 + g];
    #pragma unroll
    for (int nt = 0; nt < 8; nt++) {
        const int c = wn * 64 + nt * 8 + 2 * tig;
        const float s2a = eS2F[c],  s2b = eS2F[c + 1];
        const float mxa = eMX[c],   mxb = eMX[c + 1];
        const float rza = eRZ[c],   rzb = eRZ[c + 1];
        const float bia = __ldg(bias + c), bib = __ldg(bias + c + 1);
        #pragma unroll
        for (int mt = 0; mt < 2; mt++) {
            #pragma unroll
            for (int u = 0; u < 2; u++) {
                const int i = wm * 32 + mt * 16 + u * 8 + g;
                const float s1v = s1r[mt * 2 + u];
                const float ca = __expf(lrelu(s1v + s2a) - mxa) * rza;
                const float cb = __expf(lrelu(s1v + s2b) - mxb) * rzb;
                const float ha = acc[mt][nt][u * 2 + 0];
                const float hb = acc[mt][nt][u * 2 + 1];
                *reinterpret_cast<float2*>(&out[ob + (size_t)i * DH + c]) =
                    make_float2(fmaf(ca, ha, ha + bia), fmaf(cb, hb, hb + bib));
            }
        }
    }
}

// ===================== W -> fragment-block layout prep =====================
__global__ void wb_prep(const float* __restrict__ Wa)
{
    int t = blockIdx.x * 256 + threadIdx.x;     // 0 .. 65535
    int blk = t >> 5, l = t & 31;
    int kb = blk >> 4, nb = blk & 15;
    int n  = nb * 8 + (l >> 2);
    int k0 = kb * 16 + (l & 3) * 2;
    __half2 b0 = __floats2half2_rn(Wa[(size_t)k0 * DH + n],       Wa[(size_t)(k0 + 1) * DH + n]);
    __half2 b1 = __floats2half2_rn(Wa[(size_t)(k0 + 8) * DH + n], Wa[(size_t)(k0 + 9) * DH + n]);
    g_wb[(size_t)blk * 32 + l] = make_uint2(*reinterpret_cast<uint32_t*>(&b0),
                                            *reinterpret_cast<uint32_t*>(&b1));
}

// ===================== launch =====================
typedef CUresult (*tmap_encode_t)(CUtensorMap*, CUtensorMapDataType, cuuint32_t, void*,
                                  const cuuint64_t*, const cuuint64_t*, const cuuint32_t*,
                                  const cuuint32_t*, CUtensorMapInterleave, CUtensorMapSwizzle,
                                  CUtensorMapL2promotion, CUtensorMapFloatOOBfill);

extern "C" void kernel_launch(void* const* d_in, const int* in_sizes, int n_in,
                              void* d_out, int out_size)
{
    const float* X    = (const float*)d_in[0];
    const float* Wa   = (const float*)d_in[1];
    const float* Wb   = (const float*)d_in[2];
    const float* bb   = (const float*)d_in[3];
    const float* Wc   = (const float*)d_in[4];
    const float* bc   = (const float*)d_in[5];
    const float* bias = (const float*)d_in[6];
    float* out = (float*)d_out;

    tmap_encode_t enc = nullptr;
    cudaDriverEntryPointQueryResult qr;
    cudaGetDriverEntryPointByVersion("cuTensorMapEncodeTiled", (void**)&enc, 12000,
                                     cudaEnableDefault, &qr);
    CUtensorMap mapA;
    {
        cuuint64_t dims[2]    = {Dd, Mtot};
        cuuint64_t strides[1] = {Dd * sizeof(float)};
        cuuint32_t box[2]     = {KC, 128};         // 32 fp32 = 128 B rows = SW128 span
        cuuint32_t es[2]      = {1, 1};
        enc(&mapA, CU_TENSOR_MAP_DATA_TYPE_FLOAT32, 2, (void*)X, dims, strides, box, es,
            CU_TENSOR_MAP_INTERLEAVE_NONE, CU_TENSOR_MAP_SWIZZLE_128B,
            CU_TENSOR_MAP_L2_PROMOTION_L2_128B, CU_TENSOR_MAP_FLOAT_OOB_FILL_NONE);
    }

    wb_prep<<<256, 256>>>(Wa);

    cudaFuncSetAttribute(fused_gat, cudaFuncAttributeMaxDynamicSharedMemorySize, SMEMSZ);
    fused_gat<<<Bb, 256, SMEMSZ>>>(Wb, bb, Wc, bc, bias, out, mapA);
}